// round 7
// baseline (speedup 1.0000x reference)
#include <cuda_runtime.h>
#include <cuda_fp16.h>
#include <cstdint>

#define NN_MAX 100000
#define NE_MAX 1600000
#define D 128          // features
#define DV 32          // D/4 chunks per row (float4 for fp32, uint2(4 halves) for fp16)
#define N_ITER 40

// ---------------- static device scratch (no allocations allowed) ----------------
__device__ int    g_idx64;          // 1 if edge_index is int64, 0 if int32
__device__ int    g_mask_i32;       // 1 if mask is int32, 0 if uint8/bool
__device__ int    g_deg[NN_MAX];
__device__ int    g_rowptr[NN_MAX + 1];
__device__ int    g_cursor[NN_MAX];
__device__ float  g_dinv[NN_MAX];
__device__ float2 g_ew[NE_MAX];     // {col bit-cast, w} — one 8B broadcast load per edge
__device__ int    g_bsums[128];     // per-block partial sums for scan
__device__ int    g_boff[128];      // exclusive-scanned block offsets
__device__ int    g_total;
// fp16 ping-pong buffers (25.6 MB each). Accumulation is fp32; only storage is fp16.
__device__ __half g_h0[(size_t)NN_MAX * D];
__device__ __half g_h1[(size_t)NN_MAX * D];

// ---------------- helpers ----------------
__device__ __forceinline__ long long load_idx(const void* p, long long e) {
    if (g_idx64) return ((const long long*)p)[e];
    return (long long)((const int*)p)[e];
}
__device__ __forceinline__ bool load_mask(const void* m, int i) {
    if (g_mask_i32) return ((const int*)m)[i] != 0;
    return ((const unsigned char*)m)[i] != 0;
}

// ---------------- kernels ----------------

// Detect dtypes of edge_index and mask from bit patterns (see R0 notes).
// Parallel version: all probe loads issued concurrently by one 256-thread block
// (the old 1-thread loop was a ~320-deep dependent-load latency chain, ~40+us).
// Races on the shared flags are benign (only 1 -> 0 writes).
__global__ void detect_kernel(const void* eidx, const void* mask) {
    __shared__ int s64, smi32;
    int t = threadIdx.x;
    if (t == 0) { s64 = 1; smi32 = 1; }
    __syncthreads();
    if (t < 64) {
        if (((const int*)eidx)[2 * t + 1] != 0) s64 = 0;
    }
    if ((t & 3) != 0) {   // bytes at non-multiple-of-4 offsets
        if (((const unsigned char*)mask)[t] != 0) smi32 = 0;
    }
    __syncthreads();
    if (t == 0) { g_idx64 = s64; g_mask_i32 = smi32; }
}

__global__ void zero_kernel(int n) {
    int i = blockIdx.x * blockDim.x + threadIdx.x;
    if (i < n) { g_deg[i] = 0; g_cursor[i] = 0; }
}

__global__ void count_kernel(const void* eidx, long long ne) {
    long long e = (long long)blockIdx.x * blockDim.x + threadIdx.x;
    if (e >= ne) return;
    int r = (int)load_idx(eidx, e);
    atomicAdd(&g_deg[r], 1);
}

// ---- multi-block exclusive scan of g_deg -> g_rowptr (3 tiny kernels) ----
__global__ void __launch_bounds__(1024) scan_part_kernel(int n) {
    __shared__ int wsum[32];
    int i    = blockIdx.x * 1024 + threadIdx.x;
    int lane = threadIdx.x & 31;
    int wid  = threadIdx.x >> 5;
    int v = (i < n) ? g_deg[i] : 0;
    int s = v;
    #pragma unroll
    for (int off = 1; off < 32; off <<= 1) {
        int t = __shfl_up_sync(0xffffffffu, s, off);
        if (lane >= off) s += t;
    }
    if (lane == 31) wsum[wid] = s;
    __syncthreads();
    if (wid == 0) {
        int ws = wsum[lane];
        #pragma unroll
        for (int off = 1; off < 32; off <<= 1) {
            int t = __shfl_up_sync(0xffffffffu, ws, off);
            if (lane >= off) ws += t;
        }
        wsum[lane] = ws;
    }
    __syncthreads();
    int excl = s - v + (wid > 0 ? wsum[wid - 1] : 0);
    if (i < n) {
        g_rowptr[i] = excl;
        g_dinv[i]   = (v > 0) ? rsqrtf((float)v) : 0.0f;
    }
    if (threadIdx.x == 1023) g_bsums[blockIdx.x] = excl + v;  // block total
}

__global__ void scan_tops_kernel(int nb) {
    int lane = threadIdx.x;            // 128 threads
    __shared__ int sh[128];
    int v = (lane < nb) ? g_bsums[lane] : 0;
    sh[lane] = v;
    __syncthreads();
    for (int off = 1; off < 128; off <<= 1) {
        int add = (lane >= off) ? sh[lane - off] : 0;
        __syncthreads();
        sh[lane] += add;
        __syncthreads();
    }
    if (lane < nb) g_boff[lane] = sh[lane] - v;   // exclusive
    if (lane == 0) g_total = sh[127];
}

__global__ void __launch_bounds__(1024) scan_add_kernel(int n) {
    int i = blockIdx.x * 1024 + threadIdx.x;
    if (i < n) g_rowptr[i] += g_boff[blockIdx.x];
    if (i == 0) g_rowptr[n] = g_total;
}

__global__ void scatter_kernel(const void* eidx, long long ne) {
    long long e = (long long)blockIdx.x * blockDim.x + threadIdx.x;
    if (e >= ne) return;
    int r = (int)load_idx(eidx, e);
    int c = (int)load_idx(eidx, e + ne);
    int pos = g_rowptr[r] + atomicAdd(&g_cursor[r], 1);
    g_ew[pos] = make_float2(__int_as_float(c), g_dinv[r] * g_dinv[c]);
}

// Init: d_out = mask ? x : 0 (fp32); both fp16 buffers get the same (masked
// rows hold half(x) forever; unmasked start at 0).
__global__ void init_kernel(const float4* __restrict__ x, float4* __restrict__ out,
                            const void* mask, int n) {
    long long i = (long long)blockIdx.x * blockDim.x + threadIdx.x;
    long long total = (long long)n * DV;
    if (i >= total) return;
    int node = (int)(i >> 5);   // i / DV
    float4 v = make_float4(0.f, 0.f, 0.f, 0.f);
    if (load_mask(mask, node)) v = x[i];
    out[i] = v;
    __half2 a = __floats2half2_rn(v.x, v.y);
    __half2 b = __floats2half2_rn(v.z, v.w);
    uint2 packed;
    packed.x = *reinterpret_cast<unsigned int*>(&a);
    packed.y = *reinterpret_cast<unsigned int*>(&b);
    ((uint2*)g_h0)[i] = packed;
    ((uint2*)g_h1)[i] = packed;
}

// One warp per row; lane owns 4 features (4 halves = one 8B load per gather).
// fp32 accumulate, unroll-2 (proven — R4 showed unroll-4 regresses).
// Edge metadata is one float2 (8B) broadcast LDG per edge: 2 LDG per loop
// iteration instead of R5's 4 (LSU-issue bound regime).
// FINAL=false: write fp16 to next buffer. FINAL=true: write fp32 to d_out.
template <bool FINAL>
__global__ void __launch_bounds__(256) spmm_h_kernel(const __half* __restrict__ prev,
                                                     __half* __restrict__ nexth,
                                                     float4* __restrict__ outf,
                                                     const void* mask, int n) {
    int warp = (blockIdx.x * blockDim.x + threadIdx.x) >> 5;
    int lane = threadIdx.x & 31;
    if (warp >= n) return;
    if (load_mask(mask, warp)) return;

    int s = g_rowptr[warp];
    int e = g_rowptr[warp + 1];
    const uint2* rp = (const uint2*)prev;   // 4 halves per uint2; 32 per row

    float4 acc0 = make_float4(0.f, 0.f, 0.f, 0.f);
    float4 acc1 = make_float4(0.f, 0.f, 0.f, 0.f);
    int j = s;
    for (; j + 1 < e; j += 2) {
        float2 e0 = __ldg(&g_ew[j]);
        float2 e1 = __ldg(&g_ew[j + 1]);
        int c0 = __float_as_int(e0.x);
        int c1 = __float_as_int(e1.x);
        uint2 r0 = __ldg(&rp[(long long)c0 * DV + lane]);
        uint2 r1 = __ldg(&rp[(long long)c1 * DV + lane]);
        float2 f0a = __half22float2(*reinterpret_cast<__half2*>(&r0.x));
        float2 f0b = __half22float2(*reinterpret_cast<__half2*>(&r0.y));
        float2 f1a = __half22float2(*reinterpret_cast<__half2*>(&r1.x));
        float2 f1b = __half22float2(*reinterpret_cast<__half2*>(&r1.y));
        acc0.x = fmaf(e0.y, f0a.x, acc0.x); acc0.y = fmaf(e0.y, f0a.y, acc0.y);
        acc0.z = fmaf(e0.y, f0b.x, acc0.z); acc0.w = fmaf(e0.y, f0b.y, acc0.w);
        acc1.x = fmaf(e1.y, f1a.x, acc1.x); acc1.y = fmaf(e1.y, f1a.y, acc1.y);
        acc1.z = fmaf(e1.y, f1b.x, acc1.z); acc1.w = fmaf(e1.y, f1b.y, acc1.w);
    }
    if (j < e) {
        float2 e0 = __ldg(&g_ew[j]);
        int c0 = __float_as_int(e0.x);
        uint2 r0 = __ldg(&rp[(long long)c0 * DV + lane]);
        float2 f0a = __half22float2(*reinterpret_cast<__half2*>(&r0.x));
        float2 f0b = __half22float2(*reinterpret_cast<__half2*>(&r0.y));
        acc0.x = fmaf(e0.y, f0a.x, acc0.x); acc0.y = fmaf(e0.y, f0a.y, acc0.y);
        acc0.z = fmaf(e0.y, f0b.x, acc0.z); acc0.w = fmaf(e0.y, f0b.y, acc0.w);
    }
    acc0.x += acc1.x; acc0.y += acc1.y; acc0.z += acc1.z; acc0.w += acc1.w;

    if (FINAL) {
        outf[(long long)warp * DV + lane] = acc0;
    } else {
        __half2 a = __floats2half2_rn(acc0.x, acc0.y);
        __half2 b = __floats2half2_rn(acc0.z, acc0.w);
        uint2 packed;
        packed.x = *reinterpret_cast<unsigned int*>(&a);
        packed.y = *reinterpret_cast<unsigned int*>(&b);
        ((uint2*)nexth)[(long long)warp * DV + lane] = packed;
    }
}

// ---------------- launch ----------------
extern "C" void kernel_launch(void* const* d_in, const int* in_sizes, int n_in,
                              void* d_out, int out_size) {
    const float* x    = (const float*)d_in[0];
    const void*  eidx = d_in[1];
    const void*  mask = d_in[2];
    float*       out  = (float*)d_out;

    int       n  = in_sizes[0] / D;       // 100000
    long long ne = in_sizes[1] / 2;       // 1600000

    __half* h0 = nullptr;
    __half* h1 = nullptr;
    cudaGetSymbolAddress((void**)&h0, g_h0);
    cudaGetSymbolAddress((void**)&h1, g_h1);

    // preprocessing (once per launch, amortized over 40 iterations)
    detect_kernel<<<1, 256>>>(eidx, mask);
    zero_kernel<<<(n + 255) / 256, 256>>>(n);
    count_kernel<<<(int)((ne + 255) / 256), 256>>>(eidx, ne);

    int nb = (n + 1023) / 1024;           // 98 blocks
    scan_part_kernel<<<nb, 1024>>>(n);
    scan_tops_kernel<<<1, 128>>>(nb);
    scan_add_kernel<<<nb, 1024>>>(n);

    scatter_kernel<<<(int)((ne + 255) / 256), 256>>>(eidx, ne);

    long long tot4 = (long long)n * DV;
    init_kernel<<<(int)((tot4 + 255) / 256), 256>>>((const float4*)x, (float4*)out, mask, n);

    // 40 iterations in fp16 ping-pong; final iteration writes fp32 into d_out.
    // iter k reads h[k&1], writes h[(k+1)&1]; iter 39 reads h1, writes d_out.
    int grid = (n * 32 + 255) / 256;  // 8 warps (rows) per 256-thread CTA
    for (int it = 0; it < N_ITER - 1; it++) {
        const __half* prev = (it & 1) ? h1 : h0;
        __half*       next = (it & 1) ? h0 : h1;
        spmm_h_kernel<false><<<grid, 256>>>(prev, next, nullptr, mask, n);
    }
    spmm_h_kernel<true><<<grid, 256>>>(h1, nullptr, (float4*)out, mask, n);
}

// round 8
// speedup vs baseline: 1.4052x; 1.4052x over previous
#include <cuda_runtime.h>
#include <cuda_fp16.h>
#include <cstdint>

#define NN_MAX 100000
#define NE_MAX 1600000
#define D 128          // features
#define DV 32          // D/4 chunks per row (float4 for fp32, uint2(4 halves) for fp16)
#define N_ITER 40
#define NBIN 64        // degree bins for counting sort

// ---------------- static device scratch (no allocations allowed) ----------------
__device__ int    g_idx64;          // 1 if edge_index is int64, 0 if int32
__device__ int    g_mask_i32;       // 1 if mask is int32, 0 if uint8/bool
__device__ int    g_deg[NN_MAX];
__device__ int    g_rowptr[NN_MAX + 1];
__device__ int    g_cursor[NN_MAX];
__device__ float  g_dinv[NN_MAX];
__device__ int    g_col[NE_MAX];    // PROTECTED layout: separate col/w arrays.
__device__ float  g_w[NE_MAX];      // Interleaved float2 regressed twice (R4, R7).
__device__ int    g_bsums[128];     // per-block partial sums for scan
__device__ int    g_boff[128];      // exclusive-scanned block offsets
__device__ int    g_total;
// degree-sorted compaction of unmasked rows
__device__ int    g_dcnt[NBIN];
__device__ int    g_dcur[NBIN];
__device__ int    g_doff[NBIN];
__device__ int    g_nrows;
__device__ int    g_rows[NN_MAX];
// fp16 ping-pong buffers (25.6 MB each). Accumulation is fp32; only storage is fp16.
__device__ __half g_h0[(size_t)NN_MAX * D];
__device__ __half g_h1[(size_t)NN_MAX * D];

// ---------------- helpers ----------------
__device__ __forceinline__ long long load_idx(const void* p, long long e) {
    if (g_idx64) return ((const long long*)p)[e];
    return (long long)((const int*)p)[e];
}
__device__ __forceinline__ bool load_mask(const void* m, int i) {
    if (g_mask_i32) return ((const int*)m)[i] != 0;
    return ((const unsigned char*)m)[i] != 0;
}

// ---------------- kernels ----------------

// Detect dtypes of edge_index and mask from bit patterns (see R0 notes).
// Parallel probes; races on shared flags are benign (only 1 -> 0 writes).
__global__ void detect_kernel(const void* eidx, const void* mask) {
    __shared__ int s64, smi32;
    int t = threadIdx.x;
    if (t == 0) { s64 = 1; smi32 = 1; }
    __syncthreads();
    if (t < 64) {
        if (((const int*)eidx)[2 * t + 1] != 0) s64 = 0;
    }
    if ((t & 3) != 0) {   // bytes at non-multiple-of-4 offsets
        if (((const unsigned char*)mask)[t] != 0) smi32 = 0;
    }
    __syncthreads();
    if (t == 0) { g_idx64 = s64; g_mask_i32 = smi32; }
}

__global__ void zero_kernel(int n) {
    int i = blockIdx.x * blockDim.x + threadIdx.x;
    if (i < n) { g_deg[i] = 0; g_cursor[i] = 0; }
    if (i < NBIN) { g_dcnt[i] = 0; g_dcur[i] = 0; }
}

__global__ void count_kernel(const void* eidx, long long ne) {
    long long e = (long long)blockIdx.x * blockDim.x + threadIdx.x;
    if (e >= ne) return;
    int r = (int)load_idx(eidx, e);
    atomicAdd(&g_deg[r], 1);
}

// ---- multi-block exclusive scan of g_deg -> g_rowptr (3 tiny kernels) ----
__global__ void __launch_bounds__(1024) scan_part_kernel(int n) {
    __shared__ int wsum[32];
    int i    = blockIdx.x * 1024 + threadIdx.x;
    int lane = threadIdx.x & 31;
    int wid  = threadIdx.x >> 5;
    int v = (i < n) ? g_deg[i] : 0;
    int s = v;
    #pragma unroll
    for (int off = 1; off < 32; off <<= 1) {
        int t = __shfl_up_sync(0xffffffffu, s, off);
        if (lane >= off) s += t;
    }
    if (lane == 31) wsum[wid] = s;
    __syncthreads();
    if (wid == 0) {
        int ws = wsum[lane];
        #pragma unroll
        for (int off = 1; off < 32; off <<= 1) {
            int t = __shfl_up_sync(0xffffffffu, ws, off);
            if (lane >= off) ws += t;
        }
        wsum[lane] = ws;
    }
    __syncthreads();
    int excl = s - v + (wid > 0 ? wsum[wid - 1] : 0);
    if (i < n) {
        g_rowptr[i] = excl;
        g_dinv[i]   = (v > 0) ? rsqrtf((float)v) : 0.0f;
    }
    if (threadIdx.x == 1023) g_bsums[blockIdx.x] = excl + v;  // block total
}

__global__ void scan_tops_kernel(int nb) {
    int lane = threadIdx.x;            // 128 threads
    __shared__ int sh[128];
    int v = (lane < nb) ? g_bsums[lane] : 0;
    sh[lane] = v;
    __syncthreads();
    for (int off = 1; off < 128; off <<= 1) {
        int add = (lane >= off) ? sh[lane - off] : 0;
        __syncthreads();
        sh[lane] += add;
        __syncthreads();
    }
    if (lane < nb) g_boff[lane] = sh[lane] - v;   // exclusive
    if (lane == 0) g_total = sh[127];
}

__global__ void __launch_bounds__(1024) scan_add_kernel(int n) {
    int i = blockIdx.x * 1024 + threadIdx.x;
    if (i < n) g_rowptr[i] += g_boff[blockIdx.x];
    if (i == 0) g_rowptr[n] = g_total;
}

__global__ void scatter_kernel(const void* eidx, long long ne) {
    long long e = (long long)blockIdx.x * blockDim.x + threadIdx.x;
    if (e >= ne) return;
    int r = (int)load_idx(eidx, e);
    int c = (int)load_idx(eidx, e + ne);
    int pos = g_rowptr[r] + atomicAdd(&g_cursor[r], 1);
    g_col[pos] = c;
    g_w[pos]   = g_dinv[r] * g_dinv[c];
}

// ---- degree-sorted compaction of unmasked rows (counting sort, 64 bins) ----
__global__ void hist_kernel(const void* mask, int n) {
    int i = blockIdx.x * blockDim.x + threadIdx.x;
    if (i >= n) return;
    if (load_mask(mask, i)) return;
    int b = min(g_deg[i], NBIN - 1);
    atomicAdd(&g_dcnt[b], 1);
}

// Descending bin offsets: off[b] = sum of counts of bins with HIGHER degree
// (big rows scheduled first). One 64-thread block.
__global__ void dscan_kernel() {
    __shared__ int sh[NBIN];
    int t = threadIdx.x;               // 64 threads
    int v = g_dcnt[t];
    sh[t] = v;
    __syncthreads();
    // suffix sums: sh[t] = sum_{b>=t} cnt[b]
    for (int off = 1; off < NBIN; off <<= 1) {
        int add = (t + off < NBIN) ? sh[t + off] : 0;
        __syncthreads();
        sh[t] += add;
        __syncthreads();
    }
    g_doff[t] = sh[t] - v;             // exclusive-from-above
    if (t == 0) g_nrows = sh[0];
}

__global__ void rowfill_kernel(const void* mask, int n) {
    int i = blockIdx.x * blockDim.x + threadIdx.x;
    if (i >= n) return;
    if (load_mask(mask, i)) return;
    int b = min(g_deg[i], NBIN - 1);
    int pos = g_doff[b] + atomicAdd(&g_dcur[b], 1);
    g_rows[pos] = i;
}

// Init: d_out = mask ? x : 0 (fp32); both fp16 buffers get the same (masked
// rows hold half(x) forever; unmasked start at 0).
__global__ void init_kernel(const float4* __restrict__ x, float4* __restrict__ out,
                            const void* mask, int n) {
    long long i = (long long)blockIdx.x * blockDim.x + threadIdx.x;
    long long total = (long long)n * DV;
    if (i >= total) return;
    int node = (int)(i >> 5);   // i / DV
    float4 v = make_float4(0.f, 0.f, 0.f, 0.f);
    if (load_mask(mask, node)) v = x[i];
    out[i] = v;
    __half2 a = __floats2half2_rn(v.x, v.y);
    __half2 b = __floats2half2_rn(v.z, v.w);
    uint2 packed;
    packed.x = *reinterpret_cast<unsigned int*>(&a);
    packed.y = *reinterpret_cast<unsigned int*>(&b);
    ((uint2*)g_h0)[i] = packed;
    ((uint2*)g_h1)[i] = packed;
}

// One warp per UNMASKED row (via g_rows, degree-sorted so CTA-mates match).
// R6-exact mainloop: separate col/w arrays, unroll-2, fp32 accumulate.
// FINAL=false: write fp16 to next buffer. FINAL=true: write fp32 to d_out.
template <bool FINAL>
__global__ void __launch_bounds__(256) spmm_h_kernel(const __half* __restrict__ prev,
                                                     __half* __restrict__ nexth,
                                                     float4* __restrict__ outf) {
    int widx = (blockIdx.x * blockDim.x + threadIdx.x) >> 5;
    int lane = threadIdx.x & 31;
    if (widx >= g_nrows) return;
    int row = g_rows[widx];

    int s = g_rowptr[row];
    int e = g_rowptr[row + 1];
    const uint2* rp = (const uint2*)prev;   // 4 halves per uint2; 32 per row

    float4 acc0 = make_float4(0.f, 0.f, 0.f, 0.f);
    float4 acc1 = make_float4(0.f, 0.f, 0.f, 0.f);
    int j = s;
    for (; j + 1 < e; j += 2) {
        int   c0 = __ldg(&g_col[j]);
        float w0 = __ldg(&g_w[j]);
        int   c1 = __ldg(&g_col[j + 1]);
        float w1 = __ldg(&g_w[j + 1]);
        uint2 r0 = __ldg(&rp[(long long)c0 * DV + lane]);
        uint2 r1 = __ldg(&rp[(long long)c1 * DV + lane]);
        float2 f0a = __half22float2(*reinterpret_cast<__half2*>(&r0.x));
        float2 f0b = __half22float2(*reinterpret_cast<__half2*>(&r0.y));
        float2 f1a = __half22float2(*reinterpret_cast<__half2*>(&r1.x));
        float2 f1b = __half22float2(*reinterpret_cast<__half2*>(&r1.y));
        acc0.x = fmaf(w0, f0a.x, acc0.x); acc0.y = fmaf(w0, f0a.y, acc0.y);
        acc0.z = fmaf(w0, f0b.x, acc0.z); acc0.w = fmaf(w0, f0b.y, acc0.w);
        acc1.x = fmaf(w1, f1a.x, acc1.x); acc1.y = fmaf(w1, f1a.y, acc1.y);
        acc1.z = fmaf(w1, f1b.x, acc1.z); acc1.w = fmaf(w1, f1b.y, acc1.w);
    }
    if (j < e) {
        int   c0 = __ldg(&g_col[j]);
        float w0 = __ldg(&g_w[j]);
        uint2 r0 = __ldg(&rp[(long long)c0 * DV + lane]);
        float2 f0a = __half22float2(*reinterpret_cast<__half2*>(&r0.x));
        float2 f0b = __half22float2(*reinterpret_cast<__half2*>(&r0.y));
        acc0.x = fmaf(w0, f0a.x, acc0.x); acc0.y = fmaf(w0, f0a.y, acc0.y);
        acc0.z = fmaf(w0, f0b.x, acc0.z); acc0.w = fmaf(w0, f0b.y, acc0.w);
    }
    acc0.x += acc1.x; acc0.y += acc1.y; acc0.z += acc1.z; acc0.w += acc1.w;

    if (FINAL) {
        outf[(long long)row * DV + lane] = acc0;
    } else {
        __half2 a = __floats2half2_rn(acc0.x, acc0.y);
        __half2 b = __floats2half2_rn(acc0.z, acc0.w);
        uint2 packed;
        packed.x = *reinterpret_cast<unsigned int*>(&a);
        packed.y = *reinterpret_cast<unsigned int*>(&b);
        ((uint2*)nexth)[(long long)row * DV + lane] = packed;
    }
}

// ---------------- launch ----------------
extern "C" void kernel_launch(void* const* d_in, const int* in_sizes, int n_in,
                              void* d_out, int out_size) {
    const float* x    = (const float*)d_in[0];
    const void*  eidx = d_in[1];
    const void*  mask = d_in[2];
    float*       out  = (float*)d_out;

    int       n  = in_sizes[0] / D;       // 100000
    long long ne = in_sizes[1] / 2;       // 1600000

    __half* h0 = nullptr;
    __half* h1 = nullptr;
    cudaGetSymbolAddress((void**)&h0, g_h0);
    cudaGetSymbolAddress((void**)&h1, g_h1);

    // preprocessing (once per launch, amortized over 40 iterations)
    detect_kernel<<<1, 256>>>(eidx, mask);
    zero_kernel<<<(n + 255) / 256, 256>>>(n);
    count_kernel<<<(int)((ne + 255) / 256), 256>>>(eidx, ne);

    int nb = (n + 1023) / 1024;           // 98 blocks
    scan_part_kernel<<<nb, 1024>>>(n);
    scan_tops_kernel<<<1, 128>>>(nb);
    scan_add_kernel<<<nb, 1024>>>(n);

    scatter_kernel<<<(int)((ne + 255) / 256), 256>>>(eidx, ne);

    // degree-sorted unmasked-row list
    hist_kernel<<<(n + 255) / 256, 256>>>(mask, n);
    dscan_kernel<<<1, NBIN>>>();
    rowfill_kernel<<<(n + 255) / 256, 256>>>(mask, n);

    long long tot4 = (long long)n * DV;
    init_kernel<<<(int)((tot4 + 255) / 256), 256>>>((const float4*)x, (float4*)out, mask, n);

    // 40 iterations in fp16 ping-pong; final iteration writes fp32 into d_out.
    // Grid sized for worst case (all rows unmasked); excess warps exit on g_nrows.
    int grid = (n * 32 + 255) / 256;  // 8 warps (rows) per 256-thread CTA
    for (int it = 0; it < N_ITER - 1; it++) {
        const __half* prev = (it & 1) ? h1 : h0;
        __half*       next = (it & 1) ? h0 : h1;
        spmm_h_kernel<false><<<grid, 256>>>(prev, next, nullptr);
    }
    spmm_h_kernel<true><<<grid, 256>>>(h1, nullptr, (float4*)out);
}